// round 3
// baseline (speedup 1.0000x reference)
#include <cuda_runtime.h>
#include <math.h>

#define NUM_STEPS 30
#define NKEYS 65536          // up to 2 batches x 15-bit morton
#define PERM_CAP (1 << 19)   // 524288 >= 280000

// ---- static device scratch (no allocation allowed) ----
__device__ float g_inv_affine[8 * 16];
__device__ int g_cnt[NKEYS];
__device__ int g_off[NKEYS];
__device__ float4 g_pos_u[PERM_CAP];   // unsorted: (px,py,pz, key as int)
__device__ float4 g_pos_s[PERM_CAP];   // sorted:   (px,py,pz, orig index as int)

// ---------------------------------------------------------------------------
// morton helpers
// ---------------------------------------------------------------------------
__device__ __forceinline__ unsigned spread3(unsigned x) {
    return (x & 1u) | ((x & 2u) << 2) | ((x & 4u) << 4) | ((x & 8u) << 6) | ((x & 16u) << 8);
}

// ---------------------------------------------------------------------------
// count: affine transform + bucket count + stage transformed position
// ---------------------------------------------------------------------------
__global__ void count_kernel(const float* __restrict__ verts,
                             const float* __restrict__ affine,
                             int B, int N, float dmax, float hmax, float wmax) {
    int gid = blockIdx.x * blockDim.x + threadIdx.x;
    long long total = (long long)B * N;
    if (gid >= total) return;
    int b = gid / N, n = gid % N;

    const float* A = affine + b * 16;
    size_t vb = ((size_t)b * N + n) * 3;
    float vx = verts[vb + 0], vy = verts[vb + 1], vz = verts[vb + 2];
    float px = A[0] * vx + A[1] * vy + A[2]  * vz + A[3];
    float py = A[4] * vx + A[5] * vy + A[6]  * vz + A[7];
    float pz = A[8] * vx + A[9] * vy + A[10] * vz + A[11];

    float pd = fminf(fmaxf(px, 0.0f), dmax);
    float ph = fminf(fmaxf(py, 0.0f), hmax);
    float pw = fminf(fmaxf(pz, 0.0f), wmax);
    unsigned cd = ((unsigned)(int)pd) >> 3;
    unsigned ch = ((unsigned)(int)ph) >> 3;
    unsigned cw = ((unsigned)(int)pw) >> 3;
    int key = b * 32768 + (int)((spread3(cd) << 2) | (spread3(ch) << 1) | spread3(cw));

    g_pos_u[gid] = make_float4(px, py, pz, __int_as_float(key));
    atomicAdd(&g_cnt[key], 1);
}

// ---------------------------------------------------------------------------
// fused: single-block exclusive scan over NKEYS + affine inverse
// ---------------------------------------------------------------------------
__global__ __launch_bounds__(1024)
void scan_fused_kernel(const float* __restrict__ affine, int B) {
    const int T = 1024;
    const int IT = NKEYS / T;          // 64
    int t = threadIdx.x;
    int base = t * IT;

    int sum = 0;
    #pragma unroll 4
    for (int i = 0; i < IT; i++) sum += g_cnt[base + i];

    // block exclusive scan of per-thread sums
    __shared__ int warp_sums[32];
    int lane = t & 31, wid = t >> 5;
    int v = sum;
    #pragma unroll
    for (int off = 1; off < 32; off <<= 1) {
        int x = __shfl_up_sync(0xffffffffu, v, off);
        if (lane >= off) v += x;
    }
    if (lane == 31) warp_sums[wid] = v;
    __syncthreads();
    if (wid == 0) {
        int w = warp_sums[lane];
        #pragma unroll
        for (int off = 1; off < 32; off <<= 1) {
            int x = __shfl_up_sync(0xffffffffu, w, off);
            if (lane >= off) w += x;
        }
        warp_sums[lane] = w;
    }
    __syncthreads();
    int excl = v - sum + (wid > 0 ? warp_sums[wid - 1] : 0);

    int run = excl;
    #pragma unroll 4
    for (int i = 0; i < IT; i++) {
        int c = g_cnt[base + i];
        g_off[base + i] = run;
        run += c;
    }

    // fold in affine inverse (threads 0..B-1)
    if (t < B) {
        int b = t;
        double m[4][8];
        #pragma unroll
        for (int i = 0; i < 4; i++) {
            #pragma unroll
            for (int j = 0; j < 4; j++) m[i][j] = (double)affine[b * 16 + i * 4 + j];
            #pragma unroll
            for (int j = 0; j < 4; j++) m[i][4 + j] = (i == j) ? 1.0 : 0.0;
        }
        for (int col = 0; col < 4; col++) {
            int piv = col;
            double best = fabs(m[col][col]);
            for (int r = col + 1; r < 4; r++) {
                double vv = fabs(m[r][col]);
                if (vv > best) { best = vv; piv = r; }
            }
            if (piv != col)
                for (int j = 0; j < 8; j++) { double tt = m[col][j]; m[col][j] = m[piv][j]; m[piv][j] = tt; }
            double inv = 1.0 / m[col][col];
            for (int j = 0; j < 8; j++) m[col][j] *= inv;
            for (int r = 0; r < 4; r++) {
                if (r == col) continue;
                double f = m[r][col];
                for (int j = 0; j < 8; j++) m[r][j] -= f * m[col][j];
            }
        }
        #pragma unroll
        for (int i = 0; i < 4; i++)
            #pragma unroll
            for (int j = 0; j < 4; j++)
                g_inv_affine[b * 16 + i * 4 + j] = (float)m[i][4 + j];
    }
}

// ---------------------------------------------------------------------------
// scatter: place (pos, orig index) in sorted order
// ---------------------------------------------------------------------------
__global__ void scatter_kernel(int total) {
    int gid = blockIdx.x * blockDim.x + threadIdx.x;
    if (gid >= total) return;
    float4 P = g_pos_u[gid];
    int key = __float_as_int(P.w);
    int pos = atomicAdd(&g_off[key], 1);
    g_pos_s[pos] = make_float4(P.x, P.y, P.z, __int_as_float(gid));
}

// ---------------------------------------------------------------------------
// integration over one point — helper used by the paired kernel
// ---------------------------------------------------------------------------
struct PtState {
    float xd, xh, xw;
    int cell;
    float c[3][8];
};

__device__ __forceinline__ void do_step(PtState& S, const float* __restrict__ base,
                                        int D, int H, int W, int HW, int DHW,
                                        float dmax, float hmax, float wmax, float scale) {
    float pdc = fminf(fmaxf(S.xd, 0.0f), dmax);
    float phc = fminf(fmaxf(S.xh, 0.0f), hmax);
    float pwc = fminf(fmaxf(S.xw, 0.0f), wmax);
    float fd0 = floorf(pdc), fh0 = floorf(phc), fw0 = floorf(pwc);
    int d0 = (int)fd0, h0 = (int)fh0, w0 = (int)fw0;
    float fd = pdc - fd0, fh = phc - fh0, fw = pwc - fw0;

    int ncell = (d0 << 20) | (h0 << 10) | w0;
    if (ncell != S.cell) {
        S.cell = ncell;
        int d1 = min(d0 + 1, D - 1);
        int h1 = min(h0 + 1, H - 1);
        int w1 = min(w0 + 1, W - 1);
        int rd0 = d0 * HW, rd1 = d1 * HW;
        int rh0 = h0 * W,  rh1 = h1 * W;
        int o[8];
        o[0] = rd0 + rh0 + w0; o[1] = rd0 + rh0 + w1;
        o[2] = rd0 + rh1 + w0; o[3] = rd0 + rh1 + w1;
        o[4] = rd1 + rh0 + w0; o[5] = rd1 + rh0 + w1;
        o[6] = rd1 + rh1 + w0; o[7] = rd1 + rh1 + w1;
        #pragma unroll
        for (int cc = 0; cc < 3; cc++) {
            const float* p = base + cc * DHW;
            #pragma unroll
            for (int k = 0; k < 8; k++) S.c[cc][k] = __ldg(p + o[k]);
        }
    }

    float omfw = 1.0f - fw, omfh = 1.0f - fh, omfd = 1.0f - fd;
    float samp[3];
    #pragma unroll
    for (int cc = 0; cc < 3; cc++) {
        float c00 = S.c[cc][0] * omfw + S.c[cc][1] * fw;
        float c01 = S.c[cc][2] * omfw + S.c[cc][3] * fw;
        float c10 = S.c[cc][4] * omfw + S.c[cc][5] * fw;
        float c11 = S.c[cc][6] * omfw + S.c[cc][7] * fw;
        float c0  = c00 * omfh + c01 * fh;
        float c1  = c10 * omfh + c11 * fh;
        samp[cc]  = c0 * omfd + c1 * fd;
    }
    S.xd += samp[0] * scale;
    S.xh += samp[1] * scale;
    S.xw += samp[2] * scale;
}

__device__ __forceinline__ void write_out(float* __restrict__ out, const PtState& S,
                                          float px, float py, float pz,
                                          int pt, int B, int N) {
    int b = pt / N, n = pt % N;
    float fix = S.xd - px, fiy = S.xh - py, fiz = S.xw - pz;
    const float* Inv = g_inv_affine + b * 16;
    float ox = Inv[0] * S.xd + Inv[1] * S.xh + Inv[2]  * S.xw + Inv[3];
    float oy = Inv[4] * S.xd + Inv[5] * S.xh + Inv[6]  * S.xw + Inv[7];
    float oz = Inv[8] * S.xd + Inv[9] * S.xh + Inv[10] * S.xw + Inv[11];
    size_t pb = ((size_t)b * N + n) * 3;
    out[pb + 0] = ox; out[pb + 1] = oy; out[pb + 2] = oz;
    size_t fb = (size_t)B * N * 3 + ((size_t)b * 3) * (size_t)N + n;
    out[fb + 0 * (size_t)N] = fix;
    out[fb + 1 * (size_t)N] = fiy;
    out[fb + 2 * (size_t)N] = fiz;
}

// ---------------------------------------------------------------------------
// main integration kernel: 2 sorted points per thread for MLP
// ---------------------------------------------------------------------------
__global__ __launch_bounds__(256)
void deform_sorted_kernel(const float* __restrict__ flow,
                          float* __restrict__ out,
                          int B, int N, int D, int H, int W, int total)
{
    int i0 = (blockIdx.x * blockDim.x + threadIdx.x) * 2;
    if (i0 >= total) return;
    int i1 = min(i0 + 1, total - 1);

    float4 P0 = g_pos_s[i0];
    float4 P1 = g_pos_s[i1];
    int pt0 = __float_as_int(P0.w);
    int pt1 = __float_as_int(P1.w);
    int b0 = pt0 / N;
    int b1 = pt1 / N;

    const int HW = H * W;
    const int DHW = D * HW;
    const float* base0 = flow + (size_t)b0 * 3 * (size_t)DHW;
    const float* base1 = flow + (size_t)b1 * 3 * (size_t)DHW;
    const float scale = 1.0f / (float)NUM_STEPS;
    const float dmax = (float)(D - 1), hmax = (float)(H - 1), wmax = (float)(W - 1);

    PtState S0, S1;
    S0.xd = P0.x; S0.xh = P0.y; S0.xw = P0.z; S0.cell = -1;
    S1.xd = P1.x; S1.xh = P1.y; S1.xw = P1.z; S1.cell = -1;

    #pragma unroll 1
    for (int s = 0; s < NUM_STEPS; s++) {
        do_step(S0, base0, D, H, W, HW, DHW, dmax, hmax, wmax, scale);
        do_step(S1, base1, D, H, W, HW, DHW, dmax, hmax, wmax, scale);
    }

    write_out(out, S0, P0.x, P0.y, P0.z, pt0, B, N);
    if (i1 != i0) write_out(out, S1, P1.x, P1.y, P1.z, pt1, B, N);
}

// ---------------------------------------------------------------------------
// fallback: original unsorted kernel (odd configurations)
// ---------------------------------------------------------------------------
__global__ __launch_bounds__(256)
void deform_plain_kernel(const float* __restrict__ verts,
                         const float* __restrict__ affine,
                         const float* __restrict__ flow,
                         float* __restrict__ out,
                         int B, int N, int D, int H, int W)
{
    int gid = blockIdx.x * blockDim.x + threadIdx.x;
    long long total = (long long)B * N;
    if (gid >= total) return;
    int b = gid / N, n = gid % N;

    const float* A = affine + b * 16;
    size_t vbase = ((size_t)b * N + n) * 3;
    float vx = verts[vbase + 0], vy = verts[vbase + 1], vz = verts[vbase + 2];
    float px = A[0] * vx + A[1] * vy + A[2]  * vz + A[3];
    float py = A[4] * vx + A[5] * vy + A[6]  * vz + A[7];
    float pz = A[8] * vx + A[9] * vy + A[10] * vz + A[11];

    const int HW = H * W;
    const int DHW = D * HW;
    const float* base = flow + (size_t)b * 3 * (size_t)DHW;
    const float scale = 1.0f / (float)NUM_STEPS;
    const float dmax = (float)(D - 1), hmax = (float)(H - 1), wmax = (float)(W - 1);

    PtState S;
    S.xd = px; S.xh = py; S.xw = pz; S.cell = -1;
    #pragma unroll 1
    for (int s = 0; s < NUM_STEPS; s++)
        do_step(S, base, D, H, W, HW, DHW, dmax, hmax, wmax, scale);
    write_out(out, S, px, py, pz, gid, B, N);
}

extern "C" void kernel_launch(void* const* d_in, const int* in_sizes, int n_in,
                              void* d_out, int out_size) {
    const float* verts  = (const float*)d_in[0];
    const float* affine = (const float*)d_in[1];
    const float* flow   = (const float*)d_in[2];
    float* out = (float*)d_out;

    int B = in_sizes[1] / 16;
    int N = in_sizes[0] / (3 * B);
    long long dhw = (long long)in_sizes[2] / (3LL * B);
    int D = (int)llrint(cbrt((double)dhw));
    int H = D, W = D;
    float dmax = (float)(D - 1), hmax = (float)(H - 1), wmax = (float)(W - 1);

    long long total = (long long)B * N;
    int threads = 256;
    int blocks = (int)((total + threads - 1) / threads);

    int use_perm = (total <= PERM_CAP && D <= 256 && B <= 2) ? 1 : 0;

    if (use_perm) {
        void* cnt_ptr = nullptr;
        cudaGetSymbolAddress(&cnt_ptr, g_cnt);
        cudaMemsetAsync(cnt_ptr, 0, NKEYS * sizeof(int));
        count_kernel<<<blocks, threads>>>(verts, affine, B, N, dmax, hmax, wmax);
        scan_fused_kernel<<<1, 1024>>>(affine, B);
        scatter_kernel<<<blocks, threads>>>((int)total);
        long long pairs = (total + 1) / 2;
        int pblocks = (int)((pairs + threads - 1) / threads);
        deform_sorted_kernel<<<pblocks, threads>>>(flow, out, B, N, D, H, W, (int)total);
    } else {
        scan_fused_kernel<<<1, 1024>>>(affine, B);  // only need the inverse
        deform_plain_kernel<<<blocks, threads>>>(verts, affine, flow, out, B, N, D, H, W);
    }
}

// round 4
// speedup vs baseline: 1.9739x; 1.9739x over previous
#include <cuda_runtime.h>
#include <math.h>

#define NUM_STEPS 30
#define NKEYS_MAX 32768      // 2 batches x 24^3 linear cell keys = 27648 <= this
#define PERM_CAP (1 << 19)   // 524288 >= 280000

// ---- static device scratch (no allocation allowed) ----
__device__ float g_inv_affine[8 * 16];
__device__ int g_cnt[NKEYS_MAX];
__device__ int g_off[NKEYS_MAX];
__device__ float4 g_pos_u[PERM_CAP];   // unsorted: (px,py,pz, key as int)
__device__ float4 g_pos_s[PERM_CAP];   // sorted:   (px,py,pz, orig index as int)

// ---------------------------------------------------------------------------
// count: affine transform + linear 8^3-cell bucket count + stage position
// ---------------------------------------------------------------------------
__global__ void count_kernel(const float* __restrict__ verts,
                             const float* __restrict__ affine,
                             int B, int N, float dmax, float hmax, float wmax,
                             int ncd, int nch, int ncw) {
    int gid = blockIdx.x * blockDim.x + threadIdx.x;
    long long total = (long long)B * N;
    if (gid >= total) return;
    int b = gid / N, n = gid % N;

    const float* A = affine + b * 16;
    size_t vb = ((size_t)b * N + n) * 3;
    float vx = verts[vb + 0], vy = verts[vb + 1], vz = verts[vb + 2];
    float px = A[0] * vx + A[1] * vy + A[2]  * vz + A[3];
    float py = A[4] * vx + A[5] * vy + A[6]  * vz + A[7];
    float pz = A[8] * vx + A[9] * vy + A[10] * vz + A[11];

    float pd = fminf(fmaxf(px, 0.0f), dmax);
    float ph = fminf(fmaxf(py, 0.0f), hmax);
    float pw = fminf(fmaxf(pz, 0.0f), wmax);
    int cd = ((int)pd) >> 3;
    int ch = ((int)ph) >> 3;
    int cw = ((int)pw) >> 3;
    int key = ((b * ncd + cd) * nch + ch) * ncw + cw;

    g_pos_u[gid] = make_float4(px, py, pz, __int_as_float(key));
    atomicAdd(&g_cnt[key], 1);
}

// ---------------------------------------------------------------------------
// fused: single-block exclusive scan over nkeys + affine inverse
// ---------------------------------------------------------------------------
__global__ __launch_bounds__(1024)
void scan_fused_kernel(const float* __restrict__ affine, int B, int nkeys) {
    int t = threadIdx.x;
    int it = (nkeys + 1023) >> 10;       // ints per thread
    int base = t * it;
    int end = min(base + it, nkeys);

    int sum = 0;
    #pragma unroll 4
    for (int i = base; i < end; i++) sum += g_cnt[i];

    // block exclusive scan of per-thread sums
    __shared__ int warp_sums[32];
    int lane = t & 31, wid = t >> 5;
    int v = sum;
    #pragma unroll
    for (int off = 1; off < 32; off <<= 1) {
        int x = __shfl_up_sync(0xffffffffu, v, off);
        if (lane >= off) v += x;
    }
    if (lane == 31) warp_sums[wid] = v;
    __syncthreads();
    if (wid == 0) {
        int w = warp_sums[lane];
        #pragma unroll
        for (int off = 1; off < 32; off <<= 1) {
            int x = __shfl_up_sync(0xffffffffu, w, off);
            if (lane >= off) w += x;
        }
        warp_sums[lane] = w;
    }
    __syncthreads();
    int run = v - sum + (wid > 0 ? warp_sums[wid - 1] : 0);

    #pragma unroll 4
    for (int i = base; i < end; i++) {
        int c = g_cnt[i];
        g_off[i] = run;
        run += c;
    }

    // fold in affine inverse (threads 0..B-1)
    if (t < B) {
        int b = t;
        double m[4][8];
        #pragma unroll
        for (int i = 0; i < 4; i++) {
            #pragma unroll
            for (int j = 0; j < 4; j++) m[i][j] = (double)affine[b * 16 + i * 4 + j];
            #pragma unroll
            for (int j = 0; j < 4; j++) m[i][4 + j] = (i == j) ? 1.0 : 0.0;
        }
        for (int col = 0; col < 4; col++) {
            int piv = col;
            double best = fabs(m[col][col]);
            for (int r = col + 1; r < 4; r++) {
                double vv = fabs(m[r][col]);
                if (vv > best) { best = vv; piv = r; }
            }
            if (piv != col)
                for (int j = 0; j < 8; j++) { double tt = m[col][j]; m[col][j] = m[piv][j]; m[piv][j] = tt; }
            double inv = 1.0 / m[col][col];
            for (int j = 0; j < 8; j++) m[col][j] *= inv;
            for (int r = 0; r < 4; r++) {
                if (r == col) continue;
                double f = m[r][col];
                for (int j = 0; j < 8; j++) m[r][j] -= f * m[col][j];
            }
        }
        #pragma unroll
        for (int i = 0; i < 4; i++)
            #pragma unroll
            for (int j = 0; j < 4; j++)
                g_inv_affine[b * 16 + i * 4 + j] = (float)m[i][4 + j];
    }
}

// ---------------------------------------------------------------------------
// scatter: place (pos, orig index) in sorted order
// ---------------------------------------------------------------------------
__global__ void scatter_kernel(int total) {
    int gid = blockIdx.x * blockDim.x + threadIdx.x;
    if (gid >= total) return;
    float4 P = g_pos_u[gid];
    int key = __float_as_int(P.w);
    int pos = atomicAdd(&g_off[key], 1);
    g_pos_s[pos] = make_float4(P.x, P.y, P.z, __int_as_float(gid));
}

// ---------------------------------------------------------------------------
// integration step helper
// ---------------------------------------------------------------------------
struct PtState {
    float xd, xh, xw;
    int cell;
    float c[3][8];
};

__device__ __forceinline__ void do_step(PtState& S, const float* __restrict__ base,
                                        int D, int H, int W, int HW, int DHW,
                                        float dmax, float hmax, float wmax, float scale) {
    float pdc = fminf(fmaxf(S.xd, 0.0f), dmax);
    float phc = fminf(fmaxf(S.xh, 0.0f), hmax);
    float pwc = fminf(fmaxf(S.xw, 0.0f), wmax);
    float fd0 = floorf(pdc), fh0 = floorf(phc), fw0 = floorf(pwc);
    int d0 = (int)fd0, h0 = (int)fh0, w0 = (int)fw0;
    float fd = pdc - fd0, fh = phc - fh0, fw = pwc - fw0;

    int ncell = (d0 << 20) | (h0 << 10) | w0;
    if (ncell != S.cell) {
        S.cell = ncell;
        int d1 = min(d0 + 1, D - 1);
        int h1 = min(h0 + 1, H - 1);
        int w1 = min(w0 + 1, W - 1);
        int rd0 = d0 * HW, rd1 = d1 * HW;
        int rh0 = h0 * W,  rh1 = h1 * W;
        int o[8];
        o[0] = rd0 + rh0 + w0; o[1] = rd0 + rh0 + w1;
        o[2] = rd0 + rh1 + w0; o[3] = rd0 + rh1 + w1;
        o[4] = rd1 + rh0 + w0; o[5] = rd1 + rh0 + w1;
        o[6] = rd1 + rh1 + w0; o[7] = rd1 + rh1 + w1;
        #pragma unroll
        for (int cc = 0; cc < 3; cc++) {
            const float* p = base + cc * DHW;
            #pragma unroll
            for (int k = 0; k < 8; k++) S.c[cc][k] = __ldg(p + o[k]);
        }
    }

    float omfw = 1.0f - fw, omfh = 1.0f - fh, omfd = 1.0f - fd;
    float samp[3];
    #pragma unroll
    for (int cc = 0; cc < 3; cc++) {
        float c00 = S.c[cc][0] * omfw + S.c[cc][1] * fw;
        float c01 = S.c[cc][2] * omfw + S.c[cc][3] * fw;
        float c10 = S.c[cc][4] * omfw + S.c[cc][5] * fw;
        float c11 = S.c[cc][6] * omfw + S.c[cc][7] * fw;
        float c0  = c00 * omfh + c01 * fh;
        float c1  = c10 * omfh + c11 * fh;
        samp[cc]  = c0 * omfd + c1 * fd;
    }
    S.xd += samp[0] * scale;
    S.xh += samp[1] * scale;
    S.xw += samp[2] * scale;
}

__device__ __forceinline__ void write_out(float* __restrict__ out, const PtState& S,
                                          float px, float py, float pz,
                                          int pt, int B, int N) {
    int b = pt / N, n = pt % N;
    float fix = S.xd - px, fiy = S.xh - py, fiz = S.xw - pz;
    const float* Inv = g_inv_affine + b * 16;
    float ox = Inv[0] * S.xd + Inv[1] * S.xh + Inv[2]  * S.xw + Inv[3];
    float oy = Inv[4] * S.xd + Inv[5] * S.xh + Inv[6]  * S.xw + Inv[7];
    float oz = Inv[8] * S.xd + Inv[9] * S.xh + Inv[10] * S.xw + Inv[11];
    size_t pb = ((size_t)b * N + n) * 3;
    out[pb + 0] = ox; out[pb + 1] = oy; out[pb + 2] = oz;
    size_t fb = (size_t)B * N * 3 + ((size_t)b * 3) * (size_t)N + n;
    out[fb + 0 * (size_t)N] = fix;
    out[fb + 1 * (size_t)N] = fiy;
    out[fb + 2 * (size_t)N] = fiz;
}

// ---------------------------------------------------------------------------
// main integration kernel: 1 sorted point per thread
// ---------------------------------------------------------------------------
__global__ __launch_bounds__(256)
void deform_sorted_kernel(const float* __restrict__ flow,
                          float* __restrict__ out,
                          int B, int N, int D, int H, int W, int total)
{
    int gid = blockIdx.x * blockDim.x + threadIdx.x;
    if (gid >= total) return;

    float4 P = g_pos_s[gid];
    int pt = __float_as_int(P.w);
    int b = pt / N;

    const int HW = H * W;
    const int DHW = D * HW;
    const float* base = flow + (size_t)b * 3 * (size_t)DHW;
    const float scale = 1.0f / (float)NUM_STEPS;
    const float dmax = (float)(D - 1), hmax = (float)(H - 1), wmax = (float)(W - 1);

    PtState S;
    S.xd = P.x; S.xh = P.y; S.xw = P.z; S.cell = -1;

    #pragma unroll 1
    for (int s = 0; s < NUM_STEPS; s++)
        do_step(S, base, D, H, W, HW, DHW, dmax, hmax, wmax, scale);

    write_out(out, S, P.x, P.y, P.z, pt, B, N);
}

// ---------------------------------------------------------------------------
// fallback: unsorted (odd configurations)
// ---------------------------------------------------------------------------
__global__ __launch_bounds__(256)
void deform_plain_kernel(const float* __restrict__ verts,
                         const float* __restrict__ affine,
                         const float* __restrict__ flow,
                         float* __restrict__ out,
                         int B, int N, int D, int H, int W)
{
    int gid = blockIdx.x * blockDim.x + threadIdx.x;
    long long total = (long long)B * N;
    if (gid >= total) return;
    int b = gid / N, n = gid % N;

    const float* A = affine + b * 16;
    size_t vbase = ((size_t)b * N + n) * 3;
    float vx = verts[vbase + 0], vy = verts[vbase + 1], vz = verts[vbase + 2];
    float px = A[0] * vx + A[1] * vy + A[2]  * vz + A[3];
    float py = A[4] * vx + A[5] * vy + A[6]  * vz + A[7];
    float pz = A[8] * vx + A[9] * vy + A[10] * vz + A[11];

    const int HW = H * W;
    const int DHW = D * HW;
    const float* base = flow + (size_t)b * 3 * (size_t)DHW;
    const float scale = 1.0f / (float)NUM_STEPS;
    const float dmax = (float)(D - 1), hmax = (float)(H - 1), wmax = (float)(W - 1);

    PtState S;
    S.xd = px; S.xh = py; S.xw = pz; S.cell = -1;
    #pragma unroll 1
    for (int s = 0; s < NUM_STEPS; s++)
        do_step(S, base, D, H, W, HW, DHW, dmax, hmax, wmax, scale);
    write_out(out, S, px, py, pz, gid, B, N);
}

extern "C" void kernel_launch(void* const* d_in, const int* in_sizes, int n_in,
                              void* d_out, int out_size) {
    const float* verts  = (const float*)d_in[0];
    const float* affine = (const float*)d_in[1];
    const float* flow   = (const float*)d_in[2];
    float* out = (float*)d_out;

    int B = in_sizes[1] / 16;
    int N = in_sizes[0] / (3 * B);
    long long dhw = (long long)in_sizes[2] / (3LL * B);
    int D = (int)llrint(cbrt((double)dhw));
    int H = D, W = D;
    float dmax = (float)(D - 1), hmax = (float)(H - 1), wmax = (float)(W - 1);

    long long total = (long long)B * N;
    int threads = 256;
    int blocks = (int)((total + threads - 1) / threads);

    int ncd = (D + 7) >> 3, nch = (H + 7) >> 3, ncw = (W + 7) >> 3;
    long long nkeys = (long long)B * ncd * nch * ncw;
    int use_perm = (total <= PERM_CAP && nkeys <= NKEYS_MAX &&
                    D <= 1024 && H <= 1024 && W <= 1024) ? 1 : 0;

    if (use_perm) {
        void* cnt_ptr = nullptr;
        cudaGetSymbolAddress(&cnt_ptr, g_cnt);
        cudaMemsetAsync(cnt_ptr, 0, (size_t)nkeys * sizeof(int));
        count_kernel<<<blocks, threads>>>(verts, affine, B, N, dmax, hmax, wmax,
                                          ncd, nch, ncw);
        scan_fused_kernel<<<1, 1024>>>(affine, B, (int)nkeys);
        scatter_kernel<<<blocks, threads>>>((int)total);
        deform_sorted_kernel<<<blocks, threads>>>(flow, out, B, N, D, H, W, (int)total);
    } else {
        scan_fused_kernel<<<1, 1024>>>(affine, B, 0);  // only need the inverse
        deform_plain_kernel<<<blocks, threads>>>(verts, affine, flow, out, B, N, D, H, W);
    }
}

// round 5
// speedup vs baseline: 2.5056x; 1.2694x over previous
#include <cuda_runtime.h>
#include <math.h>

#define NUM_STEPS 30

typedef unsigned long long ull;

__device__ float g_inv_affine[64 * 16];

// ---------------------------------------------------------------------------
// packed f32x2 helpers (sm_103a)
// ---------------------------------------------------------------------------
__device__ __forceinline__ ull pack2(float lo, float hi) {
    ull r;
    asm("mov.b64 %0, {%1, %2};" : "=l"(r) : "f"(lo), "f"(hi));
    return r;
}
__device__ __forceinline__ void unpack2(ull v, float& lo, float& hi) {
    asm("mov.b64 {%0, %1}, %2;" : "=f"(lo), "=f"(hi) : "l"(v));
}
__device__ __forceinline__ ull mul2(ull a, ull b) {
    ull r;
    asm("mul.rn.f32x2 %0, %1, %2;" : "=l"(r) : "l"(a), "l"(b));
    return r;
}
__device__ __forceinline__ ull fma2(ull a, ull b, ull c) {
    ull r;
    asm("fma.rn.f32x2 %0, %1, %2, %3;" : "=l"(r) : "l"(a), "l"(b), "l"(c));
    return r;
}
// lerp2(a,b,t,omt) = a*omt + b*t   (per 32-bit half)
__device__ __forceinline__ ull lerp2(ull a, ull b, ull t, ull omt) {
    return fma2(b, t, mul2(a, omt));
}

// ---------------------------------------------------------------------------
// affine inverse (once per launch, tiny)
// ---------------------------------------------------------------------------
__global__ void invert_affine_kernel(const float* __restrict__ affine, int B) {
    int b = threadIdx.x;
    if (b >= B) return;
    double m[4][8];
    #pragma unroll
    for (int i = 0; i < 4; i++) {
        #pragma unroll
        for (int j = 0; j < 4; j++) m[i][j] = (double)affine[b * 16 + i * 4 + j];
        #pragma unroll
        for (int j = 0; j < 4; j++) m[i][4 + j] = (i == j) ? 1.0 : 0.0;
    }
    for (int col = 0; col < 4; col++) {
        int piv = col;
        double best = fabs(m[col][col]);
        for (int r = col + 1; r < 4; r++) {
            double v = fabs(m[r][col]);
            if (v > best) { best = v; piv = r; }
        }
        if (piv != col)
            for (int j = 0; j < 8; j++) { double t = m[col][j]; m[col][j] = m[piv][j]; m[piv][j] = t; }
        double inv = 1.0 / m[col][col];
        for (int j = 0; j < 8; j++) m[col][j] *= inv;
        for (int r = 0; r < 4; r++) {
            if (r == col) continue;
            double f = m[r][col];
            for (int j = 0; j < 8; j++) m[r][j] -= f * m[col][j];
        }
    }
    #pragma unroll
    for (int i = 0; i < 4; i++)
        #pragma unroll
        for (int j = 0; j < 4; j++)
            g_inv_affine[b * 16 + i * 4 + j] = (float)m[i][4 + j];
}

// ---------------------------------------------------------------------------
// main integration kernel
// ---------------------------------------------------------------------------
__global__ __launch_bounds__(256, 4)
void deform_kernel(const float* __restrict__ verts,
                   const float* __restrict__ affine,
                   const float* __restrict__ flow,
                   float* __restrict__ out,
                   int B, int N, int D, int H, int W)
{
    int gid = blockIdx.x * blockDim.x + threadIdx.x;
    long long total = (long long)B * N;
    if (gid >= total) return;
    int b = gid / N;
    int n = gid - b * N;

    // ---- affine transform ----
    const float* A = affine + b * 16;
    size_t vbase = ((size_t)b * N + n) * 3;
    float vx = verts[vbase + 0];
    float vy = verts[vbase + 1];
    float vz = verts[vbase + 2];

    float px = A[0] * vx + A[1] * vy + A[2]  * vz + A[3];
    float py = A[4] * vx + A[5] * vy + A[6]  * vz + A[7];
    float pz = A[8] * vx + A[9] * vy + A[10] * vz + A[11];

    const int HW  = H * W;
    const int DHW = D * HW;
    const float* base = flow + (size_t)b * 3 * (size_t)DHW;
    const float scale = 1.0f / (float)NUM_STEPS;
    const float dmax = (float)(D - 1), hmax = (float)(H - 1), wmax = (float)(W - 1);

    float xd = px, xh = py, xw = pz;

    // cached cell state
    float cfd = 1e30f, cfh = 1e30f, cfw = 1e30f;   // float origin of cached cell
    int cell = -1;
    ull  c01[8];        // packed channels 0,1 for the 8 corners
    float c2[8];        // channel 2

    #pragma unroll 1
    for (int s = 0; s < NUM_STEPS; s++) {
        float fd = xd - cfd;
        float fh = xh - cfh;
        float fw = xw - cfw;

        // fast in-cell check
        float mn = fminf(fd, fminf(fh, fw));
        float mx = fmaxf(fd, fmaxf(fh, fw));
        if (!(mn >= 0.0f && mx < 1.0f)) {
            // slow path: clamp, floor, maybe reload corners
            float pdc = fminf(fmaxf(xd, 0.0f), dmax);
            float phc = fminf(fmaxf(xh, 0.0f), hmax);
            float pwc = fminf(fmaxf(xw, 0.0f), wmax);
            float fd0 = floorf(pdc), fh0 = floorf(phc), fw0 = floorf(pwc);
            int d0 = (int)fd0, h0 = (int)fh0, w0 = (int)fw0;
            fd = pdc - fd0; fh = phc - fh0; fw = pwc - fw0;
            cfd = fd0; cfh = fh0; cfw = fw0;
            // NOTE: after this, if the point is outside the volume the next
            // fast check fails again (frac<0 or >=1), so clamping stays exact.

            int ncell = (d0 << 20) | (h0 << 10) | w0;
            if (ncell != cell) {
                cell = ncell;
                int d1 = min(d0 + 1, D - 1);
                int h1 = min(h0 + 1, H - 1);
                int w1 = min(w0 + 1, W - 1);
                int rd0 = d0 * HW, rd1 = d1 * HW;
                int rh0 = h0 * W,  rh1 = h1 * W;
                int o[8];
                o[0] = rd0 + rh0 + w0; o[1] = rd0 + rh0 + w1;
                o[2] = rd0 + rh1 + w0; o[3] = rd0 + rh1 + w1;
                o[4] = rd1 + rh0 + w0; o[5] = rd1 + rh0 + w1;
                o[6] = rd1 + rh1 + w0; o[7] = rd1 + rh1 + w1;
                const float* p0 = base;
                const float* p1 = base + DHW;
                const float* p2 = base + 2 * DHW;
                #pragma unroll
                for (int k = 0; k < 8; k++) {
                    float a0 = __ldg(p0 + o[k]);
                    float a1 = __ldg(p1 + o[k]);
                    c2[k]  = __ldg(p2 + o[k]);
                    c01[k] = pack2(a0, a1);
                }
            }
        }

        // but the frac may have been clamped above; re-clamp for border cells:
        // (in-range points: identity; border: frac forced into [0,1] already
        //  by the slow path since it recomputed from clamped coords)

        float omfw = 1.0f - fw, omfh = 1.0f - fh, omfd = 1.0f - fd;
        ull W2  = pack2(fw, fw),   OW2 = pack2(omfw, omfw);
        ull H2  = pack2(fh, fh),   OH2 = pack2(omfh, omfh);
        ull D2  = pack2(fd, fd),   OD2 = pack2(omfd, omfd);

        // packed channels 0,1
        ull l00 = lerp2(c01[0], c01[1], W2, OW2);
        ull l01 = lerp2(c01[2], c01[3], W2, OW2);
        ull l10 = lerp2(c01[4], c01[5], W2, OW2);
        ull l11 = lerp2(c01[6], c01[7], W2, OW2);
        ull m0  = lerp2(l00, l01, H2, OH2);
        ull m1  = lerp2(l10, l11, H2, OH2);
        ull r01 = lerp2(m0, m1, D2, OD2);
        float s0, s1;
        unpack2(r01, s0, s1);

        // scalar channel 2
        float q00 = c2[0] * omfw + c2[1] * fw;
        float q01 = c2[2] * omfw + c2[3] * fw;
        float q10 = c2[4] * omfw + c2[5] * fw;
        float q11 = c2[6] * omfw + c2[7] * fw;
        float q0  = q00 * omfh + q01 * fh;
        float q1  = q10 * omfh + q11 * fh;
        float s2  = q0 * omfd + q1 * fd;

        xd = fmaf(s0, scale, xd);
        xh = fmaf(s1, scale, xh);
        xw = fmaf(s2, scale, xw);
    }

    // ---- outputs ----
    float fix = xd - px, fiy = xh - py, fiz = xw - pz;

    const float* Inv = g_inv_affine + b * 16;
    float ox = Inv[0] * xd + Inv[1] * xh + Inv[2]  * xw + Inv[3];
    float oy = Inv[4] * xd + Inv[5] * xh + Inv[6]  * xw + Inv[7];
    float oz = Inv[8] * xd + Inv[9] * xh + Inv[10] * xw + Inv[11];

    size_t pb = ((size_t)b * N + n) * 3;
    out[pb + 0] = ox;
    out[pb + 1] = oy;
    out[pb + 2] = oz;

    size_t fb = (size_t)B * N * 3 + ((size_t)b * 3) * (size_t)N + n;
    out[fb + 0 * (size_t)N] = fix;
    out[fb + 1 * (size_t)N] = fiy;
    out[fb + 2 * (size_t)N] = fiz;
}

extern "C" void kernel_launch(void* const* d_in, const int* in_sizes, int n_in,
                              void* d_out, int out_size) {
    const float* verts  = (const float*)d_in[0];
    const float* affine = (const float*)d_in[1];
    const float* flow   = (const float*)d_in[2];
    float* out = (float*)d_out;

    int B = in_sizes[1] / 16;
    int N = in_sizes[0] / (3 * B);
    long long dhw = (long long)in_sizes[2] / (3LL * B);
    int D = (int)llrint(cbrt((double)dhw));
    int H = D, W = D;

    invert_affine_kernel<<<1, 64>>>(affine, B);

    long long total = (long long)B * N;
    int threads = 256;
    int blocks = (int)((total + threads - 1) / threads);
    deform_kernel<<<blocks, threads>>>(verts, affine, flow, out, B, N, D, H, W);
}